// round 6
// baseline (speedup 1.0000x reference)
#include <cuda_runtime.h>

// NSbuilder: emit [L=256, H=512, W=512] float bitstream.
// out[t,h,w] = (thresh > rng[idx]),  m = t < new_ns_len,
//   idx = m ? t : t - new_ns_len,  thresh = m ? src_ns : src_st.
//
// R1 structure (wall-best: LDS rng table + __stcs STG.128, TC=64) with ONE
// change: regs forced <=32 so 8 CTAs/SM -> grid 1024 runs as a single wave
// (R1 had a 136-CTA second-wave tail at 6 CTAs/SM).
//
// new_ns_len is an integral-valued float in [0,256]; for integer t in
// [0,255], (float)t < nl  <=>  t < (int)nl exactly -> pure int mask.

#define HW    (512 * 512)
#define HW4   (HW / 4)        // 65536 float4 per t-plane
#define LBITS 256
#define TC    64              // t-values per block (gridDim.y = 4)

__global__ __launch_bounds__(256, 8) void nsb_kernel(
    const float* __restrict__ src_ns,
    const float* __restrict__ src_st,
    const float* __restrict__ nlen,
    const float* __restrict__ rng,
    float4* __restrict__ out)
{
    // s[i] = rng[i - 256] for i in [256,512); [0,256) is a dummy zone so the
    // merged index (m ? t : t-n) + 256 is always in-bounds without a clamp
    // (when m is true, idx = t + 256 which is the real rng[t]).
    __shared__ float s[512];
    int tid = threadIdx.x;
    s[tid]       = 0.0f;
    s[tid + 256] = rng[tid];
    __syncthreads();

    int p4 = blockIdx.x * 256 + tid;   // float4 pixel-group [0, 65536)

    float4 ns = reinterpret_cast<const float4*>(src_ns)[p4];
    float4 st = reinterpret_cast<const float4*>(src_st)[p4];
    float4 nl = reinterpret_cast<const float4*>(nlen)[p4];

    const int n0 = (int)nl.x, n1 = (int)nl.y, n2 = (int)nl.z, n3 = (int)nl.w;

    const int tbase = blockIdx.y * TC;
    float4* optr = out + (size_t)tbase * HW4 + (size_t)p4;

    #pragma unroll 4
    for (int t = tbase; t < tbase + TC; ++t) {
        float4 o;

        {
            bool  m   = t < n0;                 // == (float)t < new_ns_len (exact)
            int   idx = m ? t : (t - n0);
            float r   = s[idx + 256];
            float th  = m ? ns.x : st.x;
            o.x = (th > r) ? 1.0f : 0.0f;
        }
        {
            bool  m   = t < n1;
            int   idx = m ? t : (t - n1);
            float r   = s[idx + 256];
            float th  = m ? ns.y : st.y;
            o.y = (th > r) ? 1.0f : 0.0f;
        }
        {
            bool  m   = t < n2;
            int   idx = m ? t : (t - n2);
            float r   = s[idx + 256];
            float th  = m ? ns.z : st.z;
            o.z = (th > r) ? 1.0f : 0.0f;
        }
        {
            bool  m   = t < n3;
            int   idx = m ? t : (t - n3);
            float r   = s[idx + 256];
            float th  = m ? ns.w : st.w;
            o.w = (th > r) ? 1.0f : 0.0f;
        }

        // Streaming store (evict-first write-back): best measured wall path.
        __stcs(optr, o);
        optr += HW4;
    }
}

extern "C" void kernel_launch(void* const* d_in, const int* in_sizes, int n_in,
                              void* d_out, int out_size)
{
    const float* src_ns = (const float*)d_in[0];
    const float* src_st = (const float*)d_in[1];
    const float* nlen   = (const float*)d_in[2];
    const float* rng    = (const float*)d_in[3];
    float4* out = (float4*)d_out;

    dim3 grid(HW4 / 256, LBITS / TC);   // (256, 4) = 1024 CTAs, single wave
    nsb_kernel<<<grid, 256>>>(src_ns, src_st, nlen, rng, out);
}